// round 4
// baseline (speedup 1.0000x reference)
#include <cuda_runtime.h>
#include <cstdint>

#define NN 8192
#define DD 128
#define CAP 352
#define NDSZ (NN * DD)

// ---------------- scratch (static device globals: no runtime allocation) ----
__device__ float g_qkv[3 * NDSZ];     // Q | K | V for current layer
__device__ float g_attn[NDSZ];        // attn @ V result
__device__ int   g_deg[NN];
__device__ int   g_nbr[(size_t)NN * CAP];

// ---------------- CSR build from bool mask (layout sniffed at runtime) ------
// Diagonal is always True. Byte at offset NN+1 distinguishes 1-byte bool
// (nonzero) from any 4-byte 0/1 encoding (byte 1 of 0x00000001 / 0x3F800000
// is 0x00).
__global__ void build_csr_kernel(const unsigned char* __restrict__ mask) {
    int row = blockIdx.x;
    __shared__ int cnt;
    if (threadIdx.x == 0) cnt = 0;
    __syncthreads();

    bool bytewise = (mask[(size_t)(NN + 1)] != 0);

    if (bytewise) {
        const uint4* mrow = (const uint4*)(mask + (size_t)row * NN);
        for (int t = threadIdx.x; t < NN / 16; t += blockDim.x) {
            uint4 v = mrow[t];
            unsigned int w[4] = {v.x, v.y, v.z, v.w};
#pragma unroll
            for (int wi = 0; wi < 4; wi++) {
                unsigned int x = w[wi];
                if (x) {
#pragma unroll
                    for (int b = 0; b < 4; b++) {
                        if ((x >> (b * 8)) & 0xFFu) {
                            int pos = atomicAdd(&cnt, 1);
                            if (pos < CAP)
                                g_nbr[(size_t)row * CAP + pos] = t * 16 + wi * 4 + b;
                        }
                    }
                }
            }
        }
    } else {
        const uint4* mrow = (const uint4*)((const unsigned int*)mask + (size_t)row * NN);
        for (int t = threadIdx.x; t < NN / 4; t += blockDim.x) {
            uint4 v = mrow[t];
            unsigned int w[4] = {v.x, v.y, v.z, v.w};
#pragma unroll
            for (int wi = 0; wi < 4; wi++) {
                if (w[wi]) {
                    int pos = atomicAdd(&cnt, 1);
                    if (pos < CAP)
                        g_nbr[(size_t)row * CAP + pos] = t * 4 + wi;
                }
            }
        }
    }
    __syncthreads();
    if (threadIdx.x == 0) g_deg[row] = (cnt < CAP) ? cnt : CAP;
}

// ---------------- fp32 GEMM: C[M,128] = A[M,128] @ W[128,128] + bias --------
// BM=32, BN=128, BK=32, 256 threads, 4x4 microtile. blockIdx.y selects one of
// up to 3 (W, bias, C) triples so QKV runs as one launch. grid.x = 256 gives
// ~2 CTAs/SM (fixes the 11.9% occupancy / 44.8% issue observed at BM=64).
__global__ __launch_bounds__(256) void gemm_kernel(
    const float* __restrict__ A,
    const float* __restrict__ W0, const float* __restrict__ W1, const float* __restrict__ W2,
    const float* __restrict__ b0, const float* __restrict__ b1, const float* __restrict__ b2,
    float* __restrict__ C0, float* __restrict__ C1, float* __restrict__ C2)
{
    const float* W    = (blockIdx.y == 0) ? W0 : (blockIdx.y == 1) ? W1 : W2;
    const float* bias = (blockIdx.y == 0) ? b0 : (blockIdx.y == 1) ? b1 : b2;
    float*       C    = (blockIdx.y == 0) ? C0 : (blockIdx.y == 1) ? C1 : C2;

    __shared__ float Ast[32][36];   // transposed A tile [k][m], padded
    __shared__ float Bs[32][128];

    int tid = threadIdx.x;
    int ty = tid >> 5;    // 0..7 -> 4 rows each
    int tx = tid & 31;    // 0..31 -> 4 cols each
    int row0 = blockIdx.x * 32;

    float acc[4][4];
#pragma unroll
    for (int r = 0; r < 4; r++)
#pragma unroll
        for (int c = 0; c < 4; c++) acc[r][c] = 0.0f;

    for (int k0 = 0; k0 < 128; k0 += 32) {
        // A tile (32x32) transposed: one float4 per thread
        {
            int r  = tid >> 3;            // 0..31
            int kg = tid & 7;             // *4
            float4 v = *(const float4*)(A + (size_t)(row0 + r) * 128 + k0 + kg * 4);
            Ast[kg * 4 + 0][r] = v.x;
            Ast[kg * 4 + 1][r] = v.y;
            Ast[kg * 4 + 2][r] = v.z;
            Ast[kg * 4 + 3][r] = v.w;
        }
        // W tile (32x128): four float4 per thread
#pragma unroll
        for (int i = 0; i < 4; i++) {
            int idx = tid + i * 256;
            int kk = idx >> 5;
            int cg = idx & 31;
            *(float4*)&Bs[kk][cg * 4] =
                *(const float4*)(W + (size_t)(k0 + kk) * 128 + cg * 4);
        }
        __syncthreads();

#pragma unroll
        for (int kk = 0; kk < 32; kk++) {
            float4 a = *(const float4*)&Ast[kk][ty * 4];   // broadcast in warp
            float4 b = *(const float4*)&Bs[kk][tx * 4];
            acc[0][0] += a.x * b.x; acc[0][1] += a.x * b.y; acc[0][2] += a.x * b.z; acc[0][3] += a.x * b.w;
            acc[1][0] += a.y * b.x; acc[1][1] += a.y * b.y; acc[1][2] += a.y * b.z; acc[1][3] += a.y * b.w;
            acc[2][0] += a.z * b.x; acc[2][1] += a.z * b.y; acc[2][2] += a.z * b.z; acc[2][3] += a.z * b.w;
            acc[3][0] += a.w * b.x; acc[3][1] += a.w * b.y; acc[3][2] += a.w * b.z; acc[3][3] += a.w * b.w;
        }
        __syncthreads();
    }

    float4 bb = *(const float4*)(bias + tx * 4);
#pragma unroll
    for (int r = 0; r < 4; r++) {
        int row = row0 + ty * 4 + r;
        float4 o;
        o.x = acc[r][0] + bb.x;
        o.y = acc[r][1] + bb.y;
        o.z = acc[r][2] + bb.z;
        o.w = acc[r][3] + bb.w;
        *(float4*)(C + (size_t)row * 128 + tx * 4) = o;
    }
}

// ---------------- sparse masked-softmax attention: one CTA (128 thr) / row --
__global__ __launch_bounds__(128) void attn_kernel(
    const float* __restrict__ Q, const float* __restrict__ K,
    const float* __restrict__ V, float* __restrict__ Out)
{
    int row = blockIdx.x;
    int tid = threadIdx.x;
    int lane = tid & 31;
    int warp = tid >> 5;

    __shared__ float qs[128];
    __shared__ int   js[CAP];
    __shared__ float ss[CAP];
    __shared__ float red_max[4];
    __shared__ float red_sum[4];
    __shared__ float bc[2];

    int deg = g_deg[row];
    qs[tid] = Q[(size_t)row * 128 + tid];
    for (int n = tid; n < deg; n += 128)
        js[n] = g_nbr[(size_t)row * CAP + n];
    __syncthreads();

    // ---- scores: 8 lanes per neighbor, 4 neighbors per warp-step -----------
    // Each lane covers dims [r*16, r*16+16); 16 independent float4 loads per
    // warp-step (high MLP), only 3 shuffles per neighbor reduction.
    const float scale = 0.08838834764831845f;   // 1/sqrt(128)
    int g = lane >> 3;   // neighbor sub-slot 0..3
    int r = lane & 7;    // dim chunk 0..7
    float4 qa = *(const float4*)&qs[r * 16 + 0];
    float4 qb = *(const float4*)&qs[r * 16 + 4];
    float4 qc = *(const float4*)&qs[r * 16 + 8];
    float4 qd = *(const float4*)&qs[r * 16 + 12];

    for (int n0 = warp * 4; n0 < deg; n0 += 16) {
        int n = n0 + g;
        float s = 0.0f;
        if (n < deg) {
            const float4* kp = (const float4*)(K + (size_t)js[n] * 128 + r * 16);
            float4 k0 = kp[0], k1 = kp[1], k2 = kp[2], k3 = kp[3];
            s  = qa.x * k0.x + qa.y * k0.y + qa.z * k0.z + qa.w * k0.w;
            s += qb.x * k1.x + qb.y * k1.y + qb.z * k1.z + qb.w * k1.w;
            s += qc.x * k2.x + qc.y * k2.y + qc.z * k2.z + qc.w * k2.w;
            s += qd.x * k3.x + qd.y * k3.y + qd.z * k3.z + qd.w * k3.w;
        }
        s += __shfl_xor_sync(0xFFFFFFFFu, s, 1);
        s += __shfl_xor_sync(0xFFFFFFFFu, s, 2);
        s += __shfl_xor_sync(0xFFFFFFFFu, s, 4);
        if (r == 0 && n < deg) ss[n] = s * scale;
    }
    __syncthreads();

    // ---- block max ----------------------------------------------------------
    float m = -1e30f;
    for (int n = tid; n < deg; n += 128) m = fmaxf(m, ss[n]);
#pragma unroll
    for (int o = 16; o; o >>= 1) m = fmaxf(m, __shfl_xor_sync(0xFFFFFFFFu, m, o));
    if (lane == 0) red_max[warp] = m;
    __syncthreads();
    if (tid == 0)
        bc[0] = fmaxf(fmaxf(red_max[0], red_max[1]), fmaxf(red_max[2], red_max[3]));
    __syncthreads();
    m = bc[0];

    // ---- exp + sum ----------------------------------------------------------
    float sum = 0.0f;
    for (int n = tid; n < deg; n += 128) {
        float p = expf(ss[n] - m);
        ss[n] = p;
        sum += p;
    }
#pragma unroll
    for (int o = 16; o; o >>= 1) sum += __shfl_xor_sync(0xFFFFFFFFu, sum, o);
    if (lane == 0) red_sum[warp] = sum;
    __syncthreads();
    if (tid == 0)
        bc[1] = red_sum[0] + red_sum[1] + red_sum[2] + red_sum[3];
    __syncthreads();
    float inv_total = 1.0f / bc[1];

    // ---- O[d] = sum_n p_n * V[j_n][d], unrolled x4 for MLP ------------------
    float acc = 0.0f;
    int n = 0;
    for (; n + 4 <= deg; n += 4) {
        float p0 = ss[n], p1 = ss[n + 1], p2 = ss[n + 2], p3 = ss[n + 3];
        int j0 = js[n], j1 = js[n + 1], j2 = js[n + 2], j3 = js[n + 3];
        float v0 = V[(size_t)j0 * 128 + tid];
        float v1 = V[(size_t)j1 * 128 + tid];
        float v2 = V[(size_t)j2 * 128 + tid];
        float v3 = V[(size_t)j3 * 128 + tid];
        acc += p0 * v0 + p1 * v1 + p2 * v2 + p3 * v3;
    }
    for (; n < deg; n++)
        acc += ss[n] * V[(size_t)js[n] * 128 + tid];

    Out[(size_t)row * 128 + tid] = acc * inv_total;
}

// ---------------- launch -----------------------------------------------------
extern "C" void kernel_launch(void* const* d_in, const int* in_sizes, int n_in,
                              void* d_out, int out_size)
{
    const float*         features = (const float*)d_in[0];
    const unsigned char* mask     = (const unsigned char*)d_in[1];
    const float* Wq = (const float*)d_in[2];
    const float* bq = (const float*)d_in[3];
    const float* Wk = (const float*)d_in[4];
    const float* bk = (const float*)d_in[5];
    const float* Wv = (const float*)d_in[6];
    const float* bv = (const float*)d_in[7];
    const float* Wo = (const float*)d_in[8];
    const float* bo = (const float*)d_in[9];
    float* out = (float*)d_out;

    float *qkv_p, *attn_p;
    cudaGetSymbolAddress((void**)&qkv_p, g_qkv);
    cudaGetSymbolAddress((void**)&attn_p, g_attn);
    float* Qp = qkv_p;
    float* Kp = qkv_p + NDSZ;
    float* Vp = qkv_p + 2 * (size_t)NDSZ;

    // outputs[0] = features
    cudaMemcpyAsync(out, features, (size_t)NDSZ * sizeof(float),
                    cudaMemcpyDeviceToDevice);

    build_csr_kernel<<<NN, 256>>>(mask);

    for (int l = 0; l < 2; l++) {
        const float* h = (l == 0) ? features : out + (size_t)l * NDSZ;
        const float* Wq_l = Wq + (size_t)l * DD * DD;
        const float* Wk_l = Wk + (size_t)l * DD * DD;
        const float* Wv_l = Wv + (size_t)l * DD * DD;
        const float* Wo_l = Wo + (size_t)l * DD * DD;
        const float* bq_l = bq + (size_t)l * DD;
        const float* bk_l = bk + (size_t)l * DD;
        const float* bv_l = bv + (size_t)l * DD;
        const float* bo_l = bo + (size_t)l * DD;

        // Q, K, V projections (3 GEMMs in one launch)
        gemm_kernel<<<dim3(NN / 32, 3), 256>>>(
            h, Wq_l, Wk_l, Wv_l, bq_l, bk_l, bv_l, Qp, Kp, Vp);

        // sparse masked attention
        attn_kernel<<<NN, 128>>>(Qp, Kp, Vp, attn_p);

        // output projection -> directly into d_out slot (also next layer's h)
        float* h_next = out + (size_t)(l + 1) * NDSZ;
        gemm_kernel<<<dim3(NN / 32, 1), 256>>>(
            attn_p, Wo_l, Wo_l, Wo_l, bo_l, bo_l, bo_l, h_next, h_next, h_next);
    }
}

// round 5
// speedup vs baseline: 1.1404x; 1.1404x over previous
#include <cuda_runtime.h>
#include <cuda_fp16.h>
#include <cstdint>

#define NN 8192
#define DD 128
#define CAP 352
#define NDSZ (NN * DD)

// ---------------- scratch (static device globals: no runtime allocation) ----
__device__ float  g_q[NDSZ];          // Q fp32 (read once per row; tiny traffic)
__device__ __half g_k[NDSZ];          // K fp16 (gathered ~165x per row)
__device__ __half g_v[NDSZ];          // V fp16 (gathered ~165x per row)
__device__ float  g_attn[NDSZ];       // attn @ V result (fp32)
__device__ int    g_deg[NN];
__device__ int    g_nbr[(size_t)NN * CAP];

// ---------------- CSR build from bool mask (layout sniffed at runtime) ------
// Diagonal is always True. Byte at offset NN+1 distinguishes 1-byte bool
// (nonzero) from any 4-byte 0/1 encoding (byte 1 of 0x00000001 / 0x3F800000
// is 0x00).
__global__ void build_csr_kernel(const unsigned char* __restrict__ mask) {
    int row = blockIdx.x;
    __shared__ int cnt;
    if (threadIdx.x == 0) cnt = 0;
    __syncthreads();

    bool bytewise = (mask[(size_t)(NN + 1)] != 0);

    if (bytewise) {
        const uint4* mrow = (const uint4*)(mask + (size_t)row * NN);
        for (int t = threadIdx.x; t < NN / 16; t += blockDim.x) {
            uint4 v = mrow[t];
            unsigned int w[4] = {v.x, v.y, v.z, v.w};
#pragma unroll
            for (int wi = 0; wi < 4; wi++) {
                unsigned int x = w[wi];
                if (x) {
#pragma unroll
                    for (int b = 0; b < 4; b++) {
                        if ((x >> (b * 8)) & 0xFFu) {
                            int pos = atomicAdd(&cnt, 1);
                            if (pos < CAP)
                                g_nbr[(size_t)row * CAP + pos] = t * 16 + wi * 4 + b;
                        }
                    }
                }
            }
        }
    } else {
        const uint4* mrow = (const uint4*)((const unsigned int*)mask + (size_t)row * NN);
        for (int t = threadIdx.x; t < NN / 4; t += blockDim.x) {
            uint4 v = mrow[t];
            unsigned int w[4] = {v.x, v.y, v.z, v.w};
#pragma unroll
            for (int wi = 0; wi < 4; wi++) {
                if (w[wi]) {
                    int pos = atomicAdd(&cnt, 1);
                    if (pos < CAP)
                        g_nbr[(size_t)row * CAP + pos] = t * 4 + wi;
                }
            }
        }
    }
    __syncthreads();
    if (threadIdx.x == 0) g_deg[row] = (cnt < CAP) ? cnt : CAP;
}

// ---------------- fp32 GEMM: C[M,128] = A[M,128] @ W[128,128] + bias --------
// BM=32, BN=128, BK=32, 256 threads, 4x4 microtile (R4 version: equal speed to
// BM=64, better occupancy). blockIdx.y: 0 -> write fp32 to Cf; 1/2 -> round to
// fp16 into Ch1/Ch2 (K/V for the sparse attention gathers).
__global__ __launch_bounds__(256) void gemm_kernel(
    const float* __restrict__ A,
    const float* __restrict__ W0, const float* __restrict__ W1, const float* __restrict__ W2,
    const float* __restrict__ b0, const float* __restrict__ b1, const float* __restrict__ b2,
    float* __restrict__ Cf, __half* __restrict__ Ch1, __half* __restrict__ Ch2)
{
    const float* W    = (blockIdx.y == 0) ? W0 : (blockIdx.y == 1) ? W1 : W2;
    const float* bias = (blockIdx.y == 0) ? b0 : (blockIdx.y == 1) ? b1 : b2;

    __shared__ float Ast[32][36];   // transposed A tile [k][m], padded
    __shared__ float Bs[32][128];

    int tid = threadIdx.x;
    int ty = tid >> 5;    // 0..7 -> 4 rows each
    int tx = tid & 31;    // 0..31 -> 4 cols each
    int row0 = blockIdx.x * 32;

    float acc[4][4];
#pragma unroll
    for (int r = 0; r < 4; r++)
#pragma unroll
        for (int c = 0; c < 4; c++) acc[r][c] = 0.0f;

    for (int k0 = 0; k0 < 128; k0 += 32) {
        {
            int r  = tid >> 3;            // 0..31
            int kg = tid & 7;             // *4
            float4 v = *(const float4*)(A + (size_t)(row0 + r) * 128 + k0 + kg * 4);
            Ast[kg * 4 + 0][r] = v.x;
            Ast[kg * 4 + 1][r] = v.y;
            Ast[kg * 4 + 2][r] = v.z;
            Ast[kg * 4 + 3][r] = v.w;
        }
#pragma unroll
        for (int i = 0; i < 4; i++) {
            int idx = tid + i * 256;
            int kk = idx >> 5;
            int cg = idx & 31;
            *(float4*)&Bs[kk][cg * 4] =
                *(const float4*)(W + (size_t)(k0 + kk) * 128 + cg * 4);
        }
        __syncthreads();

#pragma unroll
        for (int kk = 0; kk < 32; kk++) {
            float4 a = *(const float4*)&Ast[kk][ty * 4];
            float4 b = *(const float4*)&Bs[kk][tx * 4];
            acc[0][0] += a.x * b.x; acc[0][1] += a.x * b.y; acc[0][2] += a.x * b.z; acc[0][3] += a.x * b.w;
            acc[1][0] += a.y * b.x; acc[1][1] += a.y * b.y; acc[1][2] += a.y * b.z; acc[1][3] += a.y * b.w;
            acc[2][0] += a.z * b.x; acc[2][1] += a.z * b.y; acc[2][2] += a.z * b.z; acc[2][3] += a.z * b.w;
            acc[3][0] += a.w * b.x; acc[3][1] += a.w * b.y; acc[3][2] += a.w * b.z; acc[3][3] += a.w * b.w;
        }
        __syncthreads();
    }

    float4 bb = *(const float4*)(bias + tx * 4);
    if (blockIdx.y == 0) {
#pragma unroll
        for (int r = 0; r < 4; r++) {
            int row = row0 + ty * 4 + r;
            float4 o;
            o.x = acc[r][0] + bb.x;
            o.y = acc[r][1] + bb.y;
            o.z = acc[r][2] + bb.z;
            o.w = acc[r][3] + bb.w;
            *(float4*)(Cf + (size_t)row * 128 + tx * 4) = o;
        }
    } else {
        __half* C = (blockIdx.y == 1) ? Ch1 : Ch2;
#pragma unroll
        for (int r = 0; r < 4; r++) {
            int row = row0 + ty * 4 + r;
            __half2 lo = __floats2half2_rn(acc[r][0] + bb.x, acc[r][1] + bb.y);
            __half2 hi = __floats2half2_rn(acc[r][2] + bb.z, acc[r][3] + bb.w);
            uint2 pk;
            pk.x = *(unsigned int*)&lo;
            pk.y = *(unsigned int*)&hi;
            *(uint2*)(C + (size_t)row * 128 + tx * 4) = pk;
        }
    }
}

// ---------------- sparse masked-softmax attention (R3 structure, fp16 K/V) --
// One CTA (128 threads) per query row.
__global__ __launch_bounds__(128) void attn_kernel(
    const float* __restrict__ Q, const __half* __restrict__ Kh,
    const __half* __restrict__ Vh, float* __restrict__ Out)
{
    int row = blockIdx.x;
    int tid = threadIdx.x;
    int lane = tid & 31;
    int warp = tid >> 5;

    __shared__ float qs[128];
    __shared__ int   js[CAP];
    __shared__ float ss[CAP];
    __shared__ float red_max[4];
    __shared__ float red_sum[4];
    __shared__ float bc[2];

    int deg = g_deg[row];
    qs[tid] = Q[(size_t)row * 128 + tid];
    for (int n = tid; n < deg; n += 128)
        js[n] = g_nbr[(size_t)row * CAP + n];
    __syncthreads();

    // scores: warp per neighbor (strided), each lane covers 4 dims (8B fp16 load)
    const float scale = 0.08838834764831845f;   // 1/sqrt(128)
    float4 q4 = ((const float4*)qs)[lane];
    for (int n = warp; n < deg; n += 4) {
        int j = js[n];
        uint2 kraw = *(const uint2*)(Kh + (size_t)j * 128 + lane * 4);
        float2 f01 = __half22float2(*(__half2*)&kraw.x);
        float2 f23 = __half22float2(*(__half2*)&kraw.y);
        float s = q4.x * f01.x + q4.y * f01.y + q4.z * f23.x + q4.w * f23.y;
#pragma unroll
        for (int o = 16; o; o >>= 1) s += __shfl_xor_sync(0xFFFFFFFFu, s, o);
        if (lane == 0) ss[n] = s * scale;
    }
    __syncthreads();

    // block max
    float m = -1e30f;
    for (int n = tid; n < deg; n += 128) m = fmaxf(m, ss[n]);
#pragma unroll
    for (int o = 16; o; o >>= 1) m = fmaxf(m, __shfl_xor_sync(0xFFFFFFFFu, m, o));
    if (lane == 0) red_max[warp] = m;
    __syncthreads();
    if (tid == 0)
        bc[0] = fmaxf(fmaxf(red_max[0], red_max[1]), fmaxf(red_max[2], red_max[3]));
    __syncthreads();
    m = bc[0];

    // exp + sum
    float sum = 0.0f;
    for (int n = tid; n < deg; n += 128) {
        float p = expf(ss[n] - m);
        ss[n] = p;
        sum += p;
    }
#pragma unroll
    for (int o = 16; o; o >>= 1) sum += __shfl_xor_sync(0xFFFFFFFFu, sum, o);
    if (lane == 0) red_sum[warp] = sum;
    __syncthreads();
    if (tid == 0)
        bc[1] = red_sum[0] + red_sum[1] + red_sum[2] + red_sum[3];
    __syncthreads();
    float inv_total = 1.0f / bc[1];

    // O[d] = sum_n p_n * V[j_n][d]   (serial loop — the R3 form that measured best)
    float acc = 0.0f;
    for (int n = 0; n < deg; n++) {
        acc += ss[n] * __half2float(Vh[(size_t)js[n] * 128 + tid]);
    }
    Out[(size_t)row * 128 + tid] = acc * inv_total;
}

// ---------------- launch -----------------------------------------------------
extern "C" void kernel_launch(void* const* d_in, const int* in_sizes, int n_in,
                              void* d_out, int out_size)
{
    const float*         features = (const float*)d_in[0];
    const unsigned char* mask     = (const unsigned char*)d_in[1];
    const float* Wq = (const float*)d_in[2];
    const float* bq = (const float*)d_in[3];
    const float* Wk = (const float*)d_in[4];
    const float* bk = (const float*)d_in[5];
    const float* Wv = (const float*)d_in[6];
    const float* bv = (const float*)d_in[7];
    const float* Wo = (const float*)d_in[8];
    const float* bo = (const float*)d_in[9];
    float* out = (float*)d_out;

    float *Qp, *attn_p;
    __half *Kp, *Vp;
    cudaGetSymbolAddress((void**)&Qp, g_q);
    cudaGetSymbolAddress((void**)&Kp, g_k);
    cudaGetSymbolAddress((void**)&Vp, g_v);
    cudaGetSymbolAddress((void**)&attn_p, g_attn);

    // outputs[0] = features
    cudaMemcpyAsync(out, features, (size_t)NDSZ * sizeof(float),
                    cudaMemcpyDeviceToDevice);

    build_csr_kernel<<<NN, 256>>>(mask);

    for (int l = 0; l < 2; l++) {
        const float* h = (l == 0) ? features : out + (size_t)l * NDSZ;
        const float* Wq_l = Wq + (size_t)l * DD * DD;
        const float* Wk_l = Wk + (size_t)l * DD * DD;
        const float* Wv_l = Wv + (size_t)l * DD * DD;
        const float* Wo_l = Wo + (size_t)l * DD * DD;
        const float* bq_l = bq + (size_t)l * DD;
        const float* bk_l = bk + (size_t)l * DD;
        const float* bv_l = bv + (size_t)l * DD;
        const float* bo_l = bo + (size_t)l * DD;

        // Q (fp32), K (fp16), V (fp16) projections in one launch
        gemm_kernel<<<dim3(NN / 32, 3), 256>>>(
            h, Wq_l, Wk_l, Wv_l, bq_l, bk_l, bv_l, Qp, Kp, Vp);

        // sparse masked attention
        attn_kernel<<<NN, 128>>>(Qp, Kp, Vp, attn_p);

        // output projection -> directly into d_out slot (also next layer's h)
        float* h_next = out + (size_t)(l + 1) * NDSZ;
        gemm_kernel<<<dim3(NN / 32, 1), 256>>>(
            attn_p, Wo_l, Wo_l, Wo_l, bo_l, bo_l, bo_l, h_next, Kp, Vp);
    }
}